// round 6
// baseline (speedup 1.0000x reference)
#include <cuda_runtime.h>

#define NB 4
#define NA 160000
#define NG 64
#define NBLK 160             // K1 blocks per batch image
#define K1_STRIDE (NBLK*256) // 40960
#define NBLK4 145            // blocks 0..144: 4 anchors/thread; 145..159: 3

// Scratch (__device__ globals; no init required by construction)
__device__ uint2         g_best[NB * NA];            // (bits of best IoU, argmax gt)
__device__ float         g_blockmax[NB * NBLK * NG]; // per-block per-gt rounded col max
__device__ unsigned char g_lowq[NB * NA];            // low-quality flags (zeroed by K1)

// All inter/denom computations use the same _rn sequence everywhere, so any
// quotient __fdividef(inter,denom) is bit-identical for a given (anchor,gt)
// in K1 (band fallback / tile winners) and K2 (rescan equality).
__device__ __forceinline__ float box_area(float4 b) {
    return __fmul_rn(__fadd_rn(b.z, -b.x), __fadd_rn(b.w, -b.y));
}

__device__ __forceinline__ void inter_denom(float4 a, float areaA, float4 g, float areaG,
                                            float& inter, float& denom) {
    float ltx = fmaxf(g.x, a.x);
    float lty = fmaxf(g.y, a.y);
    float rbx = fminf(g.z, a.z);
    float rby = fminf(g.w, a.w);
    float w = fmaxf(__fadd_rn(rbx, -ltx), 0.0f);
    float h = fmaxf(__fadd_rn(rby, -lty), 0.0f);
    inter = __fmul_rn(w, h);
    denom = __fadd_rn(__fadd_rn(areaA, areaG), -inter);
}

__device__ __forceinline__ float iou_pair(float4 a, float areaA, float4 g, float areaG) {
    float i, d;
    inter_denom(a, areaA, g, areaG, i, d);
    return __fdividef(i, d);   // inter==0 -> exactly 0
}

// ---------------------------------------------------------------------------
// K1: single full pass, DIVISION-FREE hot loop (cross-multiplied comparisons).
// Produces per-anchor (best, bestg), per-block per-gt rounded column max,
// and zeroed lowq flags.
// ---------------------------------------------------------------------------
template <int KA>
__device__ __forceinline__ void k1_body(
    const float4* __restrict__ anchors, int b, int blk, int tid,
    const float4* sg, const float* sga, unsigned int* smax)
{
    const int a0 = blk * 256 + tid;
    const int lane = tid & 31;

    float4 an[KA]; float areaA[KA];
    float iB[KA], dB[KA]; int bg[KA];
#pragma unroll
    for (int k = 0; k < KA; ++k) {
        int a = a0 + k * K1_STRIDE;
        an[k] = anchors[b * NA + a];
        areaA[k] = box_area(an[k]);
        iB[k] = 0.0f; dB[k] = 1.0f;   // champion quotient = 0
        bg[k] = 0;
        g_lowq[b * NA + a] = 0;       // each anchor touched exactly once
    }

    float gown[2] = {0.0f, 0.0f};     // rounded tile col-max for g = lane, lane+32

#pragma unroll 8
    for (int g = 0; g < NG; ++g) {
        float4 gb = sg[g];
        float  ag = sga[g];

        float cI = 0.0f, cD = 1.0f;   // this thread's col-max candidate (q=0)
#pragma unroll
        for (int k = 0; k < KA; ++k) {
            float iV, dV;
            inter_denom(an[k], areaA[k], gb, ag, iV, dV);
            if (iV > 0.0f) {
                // column max (cross-mult; tie band negligible here, see K2 note)
                if (__fmul_rn(iV, cD) > __fmul_rn(cI, dV)) { cI = iV; cD = dV; }
                // per-anchor argmax with guard band -> exact first-occurrence
                float pc = __fmul_rn(iV, dB[k]);
                float pm = __fmul_rn(iB[k], dV);
                float diff = pc - pm;
                float eps = 3e-7f * fmaxf(pc, pm);
                if (diff > eps) {
                    iB[k] = iV; dB[k] = dV; bg[k] = g;
                } else if (diff >= -eps) {      // rare: resolve with rounded quotients
                    float qV = __fdividef(iV, dV);
                    float qM = __fdividef(iB[k], dB[k]);
                    if (qV > qM) { iB[k] = iV; dB[k] = dV; bg[k] = g; }
                }
            }
        }

        // warp-reduce the (inter, denom) col-max pair
#pragma unroll
        for (int off = 16; off; off >>= 1) {
            float oI = __shfl_xor_sync(0xffffffffu, cI, off);
            float oD = __shfl_xor_sync(0xffffffffu, cD, off);
            if (__fmul_rn(oI, cD) > __fmul_rn(cI, oD)) { cI = oI; cD = oD; }
        }
        if (lane == (g & 31))
            gown[g >> 5] = __fdividef(cI, cD);   // rounded tile winner (0 if none)
    }

    // per-anchor results: one divide per anchor for threshold semantics
#pragma unroll
    for (int k = 0; k < KA; ++k) {
        int a = a0 + k * K1_STRIDE;
        float bestv = __fdividef(iB[k], dB[k]);
        g_best[b * NA + a] = make_uint2(__float_as_uint(bestv), (unsigned)bg[k]);
    }

    // block-level rounded col-max (IoU >= 0: uint order == float order)
    atomicMax(&smax[lane],      __float_as_uint(gown[0]));
    atomicMax(&smax[lane + 32], __float_as_uint(gown[1]));
}

__global__ __launch_bounds__(256, 3)
void k_main(const float4* __restrict__ anchors, const float4* __restrict__ gts)
{
    const int b = blockIdx.y;
    const int blk = blockIdx.x;
    const int tid = threadIdx.x;

    __shared__ float4 sg[NG];
    __shared__ float  sga[NG];
    __shared__ unsigned int smax[NG];

    if (tid < NG) {
        float4 g = gts[b * NG + tid];
        sg[tid] = g;
        sga[tid] = box_area(g);
        smax[tid] = 0u;
    }
    __syncthreads();

    if (blk < NBLK4) k1_body<4>(anchors, b, blk, tid, sg, sga, smax);
    else             k1_body<3>(anchors, b, blk, tid, sg, sga, smax);

    __syncthreads();
    if (tid < NG)
        g_blockmax[(b * NBLK + blk) * NG + tid] = __uint_as_float(smax[tid]);
}

// ---------------------------------------------------------------------------
// K2: sparse low-quality pass on ROUNDED quotients. One block per (gt,batch):
// find global column max from 160 rounded block maxima, rescan only blocks
// achieving it, flag anchors whose rounded quotient equals it (captures all
// rounded ties, same semantics as the reference's mq == highest_per_gt).
// ---------------------------------------------------------------------------
__global__ __launch_bounds__(256)
void k_lowq(const float4* __restrict__ anchors, const float4* __restrict__ gts)
{
    const int g = blockIdx.x;
    const int b = blockIdx.y;
    const int tid = threadIdx.x;

    __shared__ float red[256];
    __shared__ int   list[NBLK];
    __shared__ int   cnt;

    if (tid == 0) cnt = 0;
    float m = (tid < NBLK) ? g_blockmax[(b * NBLK + tid) * NG + g] : 0.0f;
    red[tid] = m;
    __syncthreads();
#pragma unroll
    for (int s = 128; s; s >>= 1) {
        if (tid < s) red[tid] = fmaxf(red[tid], red[tid + s]);
        __syncthreads();
    }
    const float shigh = red[0];

    if (tid < NBLK && m == shigh) {
        int i = atomicAdd(&cnt, 1);
        list[i] = tid;
    }
    __syncthreads();

    const int n = cnt;
    float4 gb = gts[b * NG + g];
    float  ag = box_area(gb);

    for (int i = 0; i < n; ++i) {
        int blk = list[i];
#pragma unroll
        for (int k = 0; k < 4; ++k) {
            int a = blk * 256 + k * K1_STRIDE + tid;
            if (a < NA) {
                float4 an = anchors[b * NA + a];
                float v = iou_pair(an, box_area(an), gb, ag);
                if (v == shigh) g_lowq[b * NA + a] = 1;
            }
        }
    }
}

// ---------------------------------------------------------------------------
// K3: label + matched-box writer.
// ---------------------------------------------------------------------------
__global__ __launch_bounds__(256)
void k_label(const float4* __restrict__ gts, const float* __restrict__ scores,
             const int* __restrict__ confs,
             float* __restrict__ outL, float4* __restrict__ outB)
{
    const int b = blockIdx.y;
    const int tid = threadIdx.x;

    __shared__ float4 sg[NG];
    __shared__ float  ss[NG];
    __shared__ int    sc[NG];
    if (tid < NG) {
        sg[tid] = gts[b * NG + tid];
        ss[tid] = scores[b * NG + tid];
        sc[tid] = confs[b * NG + tid];
    }
    __syncthreads();

    const int a = blockIdx.x * 256 + tid;   // NA = 625*256 exactly
    const int idx = b * NA + a;

    uint2 bb = g_best[idx];
    float best = __uint_as_float(bb.x);
    int bestg = (int)bb.y;
    bool lowq = g_lowq[idx] != 0;

    int midx = lowq ? bestg
                    : (best >= 0.7f ? bestg : (best >= 0.3f ? -2 : -1));
    int cl = midx >= 0 ? midx : 0;

    float s = ss[cl];
    int c = sc[cl];
    float label = (midx == -1) ? 0.0f
                : (midx == -2) ? -1.0f
                : ((s < 1.0f || c == 0) ? -1.0f : 1.0f);

    outL[idx] = label;
    outB[idx] = sg[cl];
}

extern "C" void kernel_launch(void* const* d_in, const int* in_sizes, int n_in,
                              void* d_out, int out_size) {
    (void)in_sizes; (void)n_in; (void)out_size;
    const float4* anchors = (const float4*)d_in[0];   // [B, A, 4] f32
    const float4* gts     = (const float4*)d_in[1];   // [B, G, 4] f32
    const float*  scores  = (const float*)d_in[2];    // [B, G] f32
    const int*    confs   = (const int*)d_in[3];      // [B, G] i32

    float*  outL = (float*)d_out;                      // labels [B, A]
    float4* outB = (float4*)((float*)d_out + NB * NA); // matched boxes [B, A, 4]

    k_main <<<dim3(NBLK, NB), 256>>>(anchors, gts);
    k_lowq <<<dim3(NG,   NB), 256>>>(anchors, gts);
    k_label<<<dim3(NA / 256, NB), 256>>>(gts, scores, confs, outL, outB);
}

// round 7
// speedup vs baseline: 3.2246x; 3.2246x over previous
#include <cuda_runtime.h>

#define NB 4
#define NA 160000
#define NG 64
#define NBLK 74              // K1 blocks per batch image (grid 74*4 = 296 = 2*148)
#define K1_STRIDE (NBLK*256) // 18944
#define NBLK9 33             // blocks 0..32: 9 anchors/thread; 33..73: 8  (33*9+41*8=625)

// Scratch (__device__ globals; no init required by construction)
__device__ uint2         g_best[NB * NA];            // (bits of best IoU, argmax gt)
__device__ float         g_blockmax[NB * NBLK * NG]; // per-block per-gt rounded col max
__device__ unsigned char g_lowq[NB * NA];            // low-quality flags (zeroed by K1)

// Same _rn sequence everywhere + __fdividef everywhere => any (anchor,gt) IoU
// is bit-identical between K1 and K2, so K2's rounded-equality rescan matches
// the reference's  mq == highest_per_gt  exactly.
__device__ __forceinline__ float box_area(float4 b) {
    return __fmul_rn(__fadd_rn(b.z, -b.x), __fadd_rn(b.w, -b.y));
}

__device__ __forceinline__ float iou_pair(float4 a, float areaA, float4 g, float areaG) {
    float ltx = fmaxf(g.x, a.x);
    float lty = fmaxf(g.y, a.y);
    float rbx = fminf(g.z, a.z);
    float rby = fminf(g.w, a.w);
    float w = fmaxf(__fadd_rn(rbx, -ltx), 0.0f);
    float h = fmaxf(__fadd_rn(rby, -lty), 0.0f);
    float inter = __fmul_rn(w, h);
    float denom = __fadd_rn(__fadd_rn(areaA, areaG), -inter);
    return __fdividef(inter, denom);   // RCP+FMUL; inter==0 -> exactly 0; denom>0 always
}

// ---------------------------------------------------------------------------
// K1: single full IoU pass on direct rounded quotients (reference semantics).
// Per thread: KA anchors in registers. Produces per-anchor (best, bestg),
// per-block per-gt rounded column max, zeroed lowq flags.
// ---------------------------------------------------------------------------
template <int KA>
__device__ __forceinline__ void k1_body(
    const float4* __restrict__ anchors, int b, int blk, int tid,
    const float4* sg, const float* sga, unsigned int* smax)
{
    const int a0 = blk * 256 + tid;
    const int lane = tid & 31;

    float4 an[KA]; float areaA[KA]; float best[KA]; int bg[KA];
#pragma unroll
    for (int k = 0; k < KA; ++k) {
        int a = a0 + k * K1_STRIDE;
        an[k] = anchors[b * NA + a];
        areaA[k] = box_area(an[k]);
        best[k] = -1.0f;               // first g always wins -> first-occurrence argmax
        bg[k] = 0;
        g_lowq[b * NA + a] = 0;        // each anchor touched exactly once
    }

    float gown[2] = {0.0f, 0.0f};      // rounded tile col-max for g = lane, lane+32

#pragma unroll 2
    for (int g = 0; g < NG; ++g) {
        float4 gb = sg[g];
        float  ag = sga[g];

        float cmax = 0.0f;             // this thread's column-max candidate
#pragma unroll
        for (int k = 0; k < KA; ++k) {
            float q = iou_pair(an[k], areaA[k], gb, ag);
            cmax = fmaxf(cmax, q);
            if (q > best[k]) { best[k] = q; bg[k] = g; }   // strict >: first occurrence
        }

        // warp-reduce the rounded column max
#pragma unroll
        for (int off = 16; off; off >>= 1)
            cmax = fmaxf(cmax, __shfl_xor_sync(0xffffffffu, cmax, off));
        if (lane == (g & 31))
            gown[g >> 5] = cmax;
    }

#pragma unroll
    for (int k = 0; k < KA; ++k) {
        int a = a0 + k * K1_STRIDE;
        g_best[b * NA + a] = make_uint2(__float_as_uint(best[k]), (unsigned)bg[k]);
    }

    // block-level rounded col-max (IoU >= 0: uint order == float order)
    atomicMax(&smax[lane],      __float_as_uint(gown[0]));
    atomicMax(&smax[lane + 32], __float_as_uint(gown[1]));
}

__global__ __launch_bounds__(256, 2)
void k_main(const float4* __restrict__ anchors, const float4* __restrict__ gts)
{
    const int b = blockIdx.y;
    const int blk = blockIdx.x;
    const int tid = threadIdx.x;

    __shared__ float4 sg[NG];
    __shared__ float  sga[NG];
    __shared__ unsigned int smax[NG];

    if (tid < NG) {
        float4 g = gts[b * NG + tid];
        sg[tid] = g;
        sga[tid] = box_area(g);
        smax[tid] = 0u;
    }
    __syncthreads();

    if (blk < NBLK9) k1_body<9>(anchors, b, blk, tid, sg, sga, smax);
    else             k1_body<8>(anchors, b, blk, tid, sg, sga, smax);

    __syncthreads();
    if (tid < NG)
        g_blockmax[(b * NBLK + blk) * NG + tid] = __uint_as_float(smax[tid]);
}

// ---------------------------------------------------------------------------
// K2: sparse low-quality pass. One block per (gt,batch) column: reduce the 74
// block maxima to the global column max, rescan only blocks achieving it, flag
// anchors whose rounded IoU equals it (exact reference semantics).
// ---------------------------------------------------------------------------
__global__ __launch_bounds__(256)
void k_lowq(const float4* __restrict__ anchors, const float4* __restrict__ gts)
{
    const int g = blockIdx.x;
    const int b = blockIdx.y;
    const int tid = threadIdx.x;

    __shared__ float red[256];
    __shared__ int   list[NBLK];
    __shared__ int   cnt;

    if (tid == 0) cnt = 0;
    float m = (tid < NBLK) ? g_blockmax[(b * NBLK + tid) * NG + g] : 0.0f;
    red[tid] = m;
    __syncthreads();
#pragma unroll
    for (int s = 128; s; s >>= 1) {
        if (tid < s) red[tid] = fmaxf(red[tid], red[tid + s]);
        __syncthreads();
    }
    const float shigh = red[0];

    if (tid < NBLK && m == shigh) {
        int i = atomicAdd(&cnt, 1);
        list[i] = tid;
    }
    __syncthreads();

    const int n = cnt;
    float4 gb = gts[b * NG + g];
    float  ag = box_area(gb);

    for (int i = 0; i < n; ++i) {
        int blk = list[i];
#pragma unroll
        for (int k = 0; k < 9; ++k) {       // covers both the 9- and 8-anchor blocks
            int a = blk * 256 + k * K1_STRIDE + tid;
            if (a < NA) {
                float4 an = anchors[b * NA + a];
                float v = iou_pair(an, box_area(an), gb, ag);
                if (v == shigh) g_lowq[b * NA + a] = 1;
            }
        }
    }
}

// ---------------------------------------------------------------------------
// K3: label + matched-box writer.
// ---------------------------------------------------------------------------
__global__ __launch_bounds__(256)
void k_label(const float4* __restrict__ gts, const float* __restrict__ scores,
             const int* __restrict__ confs,
             float* __restrict__ outL, float4* __restrict__ outB)
{
    const int b = blockIdx.y;
    const int tid = threadIdx.x;

    __shared__ float4 sg[NG];
    __shared__ float  ss[NG];
    __shared__ int    sc[NG];
    if (tid < NG) {
        sg[tid] = gts[b * NG + tid];
        ss[tid] = scores[b * NG + tid];
        sc[tid] = confs[b * NG + tid];
    }
    __syncthreads();

    const int a = blockIdx.x * 256 + tid;   // NA = 625*256 exactly
    const int idx = b * NA + a;

    uint2 bb = g_best[idx];
    float best = __uint_as_float(bb.x);
    int bestg = (int)bb.y;
    bool lowq = g_lowq[idx] != 0;

    // Matcher: <0.3 -> -1 ; <0.7 -> -2 ; else match. Low-quality override.
    int midx = lowq ? bestg
                    : (best >= 0.7f ? bestg : (best >= 0.3f ? -2 : -1));
    int cl = midx >= 0 ? midx : 0;

    float s = ss[cl];
    int c = sc[cl];
    float label = (midx == -1) ? 0.0f
                : (midx == -2) ? -1.0f
                : ((s < 1.0f || c == 0) ? -1.0f : 1.0f);

    outL[idx] = label;
    outB[idx] = sg[cl];
}

extern "C" void kernel_launch(void* const* d_in, const int* in_sizes, int n_in,
                              void* d_out, int out_size) {
    (void)in_sizes; (void)n_in; (void)out_size;
    const float4* anchors = (const float4*)d_in[0];   // [B, A, 4] f32
    const float4* gts     = (const float4*)d_in[1];   // [B, G, 4] f32
    const float*  scores  = (const float*)d_in[2];    // [B, G] f32
    const int*    confs   = (const int*)d_in[3];      // [B, G] i32

    float*  outL = (float*)d_out;                      // labels [B, A]
    float4* outB = (float4*)((float*)d_out + NB * NA); // matched boxes [B, A, 4]

    k_main <<<dim3(NBLK, NB), 256>>>(anchors, gts);
    k_lowq <<<dim3(NG,   NB), 256>>>(anchors, gts);
    k_label<<<dim3(NA / 256, NB), 256>>>(gts, scores, confs, outL, outB);
}